// round 16
// baseline (speedup 1.0000x reference)
#include <cuda_runtime.h>
#include <cstdint>

// Problem shapes (fixed by the dataset)
#define BB 64
#define QQ 512
#define CC 128
#define PP 2048
#define GG 256

#define BM 64          // Q tile (M)
#define BK 32          // persons per chunk (K of one fp8 MMA)
#define NKC (PP / BK)  // 64 chunks
#define STAGES 8       // SMEM ring depth
#define NTH 640        // 8 consumer warps + 4 producer groups x 96 threads

// Interleaved fragment image layout (validated R15 main):
//  A: 4 sections x 136 words; word = sec*136 + q*2 + h  (h: kw=sec / kw=sec+4)
//  B: 4 sections x 520 words; word = sec*520 + n*2 + h
#define A_SEC_W 136
#define A_IMG_B (4 * A_SEC_W * 4)    // 2176 B
#define B_SEC_W 520
#define B_IMG_B (4 * B_SEC_W * 4)    // 8320 B
#define STAGE_B (A_IMG_B + B_IMG_B)  // 10496 B
#define SMEM_DYN (STAGES * STAGE_B)  // 83968 B

#define L_PITCH 133  // fp32 logits epilogue pitch

// 5-op softplus (validated R10/R12: rel_err 6.43e-5); inputs N(0,1)
__device__ __forceinline__ float softplus_f(float x) {
    float e, l;
    asm("ex2.approx.f32 %0, %1;" : "=f"(e) : "f"(x * 1.4426950408889634f));
    asm("lg2.approx.f32 %0, %1;" : "=f"(l) : "f"(e + 1.0f));
    return 0.6931471805599453f * l;
}

__device__ __forceinline__ uint32_t smem_u32(const void* p) {
    return (uint32_t)__cvta_generic_to_shared(p);
}

#define MBARRIER_INIT(addr, count)                                 \
    asm volatile("mbarrier.init.shared.b64 [%0], %1;" ::"r"(addr), \
                 "r"((uint32_t)(count))                            \
                 : "memory")

#define MBARRIER_ARRIVE(addr)                                      \
    asm volatile("mbarrier.arrive.shared.b64 _, [%0];" ::"r"(addr) \
                 : "memory")

#define MBARRIER_WAIT_PARITY(mbar_addr, phase_parity)                          \
    do {                                                                       \
        uint32_t _mbar = (uint32_t)(mbar_addr);                                \
        uint32_t _parity = (uint32_t)(phase_parity);                           \
        uint32_t _done;                                                        \
        asm volatile(                                                          \
            "{\n\t"                                                            \
            ".reg .pred p;\n\t"                                                \
            "mbarrier.try_wait.parity.acquire.cta.shared::cta.b64 p, [%1], "   \
            "%2;\n\t"                                                          \
            "selp.b32 %0, 1, 0, p;\n\t"                                        \
            "}"                                                                \
            : "=r"(_done)                                                      \
            : "r"(_mbar), "r"(_parity)                                         \
            : "memory");                                                       \
        if (!_done) {                                                          \
            asm volatile(                                                      \
                "{\n\t"                                                        \
                ".reg .pred P1;\n\t"                                           \
                "WAIT_LOOP_%=:\n\t"                                            \
                "mbarrier.try_wait.parity.acquire.cta.shared::cta.b64 P1, "    \
                "[%0], %1, 0x989680;\n\t"                                      \
                "@P1 bra.uni WAIT_DONE_%=;\n\t"                                \
                "bra.uni WAIT_LOOP_%=;\n\t"                                    \
                "WAIT_DONE_%=:\n\t"                                            \
                "}" ::"r"(_mbar),                                              \
                "r"(_parity)                                                   \
                : "memory");                                                   \
        }                                                                      \
    } while (0)

// pack 4 fp32 -> 4 e4m3 bytes, byte0 = f0 .. byte3 = f3 (validated R9/R15)
__device__ __forceinline__ uint32_t pack_e4m3(float f0, float f1, float f2,
                                              float f3) {
    unsigned short lo, hi;
    asm("cvt.rn.satfinite.e4m3x2.f32 %0, %1, %2;" : "=h"(lo) : "f"(f1), "f"(f0));
    asm("cvt.rn.satfinite.e4m3x2.f32 %0, %1, %2;" : "=h"(hi) : "f"(f3), "f"(f2));
    return (uint32_t)lo | ((uint32_t)hi << 16);
}

#define STS128(addr, w0, w1, w2, w3)                                       \
    asm volatile("st.shared.v4.b32 [%0], {%1, %2, %3, %4};" ::"r"(addr),   \
                 "r"(w0), "r"(w1), "r"(w2), "r"(w3)                        \
                 : "memory")

#define LDS64(lo, hi, addr)                                        \
    asm volatile("ld.shared.v2.b32 {%0, %1}, [%2];"                \
                 : "=r"(lo), "=r"(hi)                              \
                 : "r"(addr))

// fp8 MMA: D(16x8,f32) += A(16x32,e4m3) * B(32x8,e4m3)  (sm_89 baseline op)
__device__ __forceinline__ void mma_e4m3(float* d, const uint32_t* a,
                                         const uint32_t* b) {
    asm volatile(
        "mma.sync.aligned.m16n8k32.row.col.f32.e4m3.e4m3.f32 "
        "{%0,%1,%2,%3}, {%4,%5,%6,%7}, {%8,%9}, {%0,%1,%2,%3};"
        : "+f"(d[0]), "+f"(d[1]), "+f"(d[2]), "+f"(d[3])
        : "r"(a[0]), "r"(a[1]), "r"(a[2]), "r"(a[3]), "r"(b[0]), "r"(b[1]));
}

// ---------------------------------------------------------------------------
// Single fused kernel: fp8 GEMM + softplus(attw) + softplus(logits) + gather
// 8 consumer warps (R15 LDS.64 path) + 4x96 producer threads (role-split A/B)
// ---------------------------------------------------------------------------
extern "C" __global__ void __launch_bounds__(NTH, 1)
cost_kernel(const float* __restrict__ logits, const float* __restrict__ attw,
            const float* __restrict__ onehot, const int* __restrict__ ids,
            float* __restrict__ out) {
    extern __shared__ __align__(16) char dynsmem[];
    const uint32_t base = smem_u32(dynsmem);

    __shared__ alignas(8) unsigned long long bar_full[STAGES];
    __shared__ alignas(8) unsigned long long bar_empty[STAGES];
    __shared__ float s_sp[BM];  // sum_p softplus(attw[:,q])
    __shared__ float s_sa[BM];  // sum_c softplus(logits[q,:])
    __shared__ int s_ids[GG];

    const int tid = threadIdx.x;
    const int lane = tid & 31;
    const int warp = tid >> 5;
    const int q0 = blockIdx.x * BM;
    const int b = blockIdx.y;

    if (tid < BM) s_sp[tid] = 0.0f;
    if (tid == 0) {
#pragma unroll
        for (int s = 0; s < STAGES; s++) {
            MBARRIER_INIT(smem_u32(&bar_full[s]), 96);  // one producer group
            MBARRIER_INIT(smem_u32(&bar_empty[s]), 8);  // 8 consumer warps
        }
    }
    __syncthreads();

    float acc[2][8][4];
    const int wm = warp >> 2;  // 0..1 (consumers)
    const int wn = warp & 3;   // 0..3
    const int g = lane >> 2;   // 0..7
    const int tig = lane & 3;  // 0..3

    if (warp < 8) {
        // ===================== CONSUMERS (warps 0..7) ======================
#pragma unroll
        for (int i = 0; i < 2; i++)
#pragma unroll
            for (int j = 0; j < 8; j++)
#pragma unroll
                for (int k = 0; k < 4; k++) acc[i][j][k] = 0.0f;

        // lane-constant fragment byte offsets within a stage (R15 layout)
        const uint32_t aOff = tig * (A_SEC_W * 4) + (wm * 32 + g) * 8;
        const uint32_t bOff = A_IMG_B + tig * (B_SEC_W * 4) + (wn * 64 + g) * 8;

        for (int kc = 0; kc < NKC; ++kc) {
            const int st = kc & (STAGES - 1);
            MBARRIER_WAIT_PARITY(smem_u32(&bar_full[st]), (kc >> 3) & 1);

            const uint32_t sb = base + st * STAGE_B;
            const uint32_t aA = sb + aOff;
            const uint32_t bA = sb + bOff;

            uint32_t aF[2][4];
#pragma unroll
            for (int mt = 0; mt < 2; mt++) {
                LDS64(aF[mt][0], aF[mt][2], aA + mt * 128);       // m
                LDS64(aF[mt][1], aF[mt][3], aA + mt * 128 + 64);  // m+8
            }
            // B fragments in two halves (register pressure)
#pragma unroll
            for (int half = 0; half < 2; half++) {
                uint32_t bF[4][2];
#pragma unroll
                for (int nt = 0; nt < 4; nt++)
                    LDS64(bF[nt][0], bF[nt][1], bA + (half * 4 + nt) * 64);
#pragma unroll
                for (int mt = 0; mt < 2; mt++)
#pragma unroll
                    for (int nt = 0; nt < 4; nt++)
                        mma_e4m3(acc[mt][half * 4 + nt], aF[mt], bF[nt]);
            }

            __syncwarp();
            if (lane == 0) MBARRIER_ARRIVE(smem_u32(&bar_empty[st]));
        }
    } else {
        // ============ PRODUCERS: 4 groups x 96 (64 B-role + 32 A-role) =====
        const int pid = tid - 256;    // 0..383
        const int group = pid / 96;   // 0..3 ; handles kc % 4 == group
        const int pt = pid % 96;      // 0..95

        const float4* a4 = reinterpret_cast<const float4*>(attw) +
                           (size_t)b * PP * (QQ / 4);
        const float4* b4 = reinterpret_cast<const float4*>(onehot) +
                           (size_t)b * PP * (GG / 4);

        if (pt < 64) {
            // ---------------- B-role: convert onehot chunk -----------------
            const int gq = pt;  // g-quad 0..63
            for (int t = 0; t < NKC / 4; ++t) {
                const int kc = group + 4 * t;
                const int st = kc & (STAGES - 1);
                const int p0 = kc * BK;

                // preload section 0 rows before the wait
                float4 r[8];
#pragma unroll
                for (int j = 0; j < 4; j++)
                    r[j] = b4[(size_t)(p0 + j) * (GG / 4) + gq];
#pragma unroll
                for (int j = 0; j < 4; j++)
                    r[4 + j] = b4[(size_t)(p0 + 16 + j) * (GG / 4) + gq];

                MBARRIER_WAIT_PARITY(smem_u32(&bar_empty[st]),
                                     ((kc >> 3) + 1) & 1);
                const uint32_t bdst =
                    base + st * STAGE_B + A_IMG_B + gq * 32;

#pragma unroll
                for (int sec = 0; sec < 4; sec++) {
                    float4 nr[8];
                    if (sec < 3) {
                        const int pr = p0 + 4 * (sec + 1);
#pragma unroll
                        for (int j = 0; j < 4; j++)
                            nr[j] = b4[(size_t)(pr + j) * (GG / 4) + gq];
#pragma unroll
                        for (int j = 0; j < 4; j++)
                            nr[4 + j] =
                                b4[(size_t)(pr + 16 + j) * (GG / 4) + gq];
                    }
                    uint32_t w[8];
#pragma unroll
                    for (int c = 0; c < 4; c++) {
                        w[2 * c + 0] = pack_e4m3((&r[0].x)[c], (&r[1].x)[c],
                                                 (&r[2].x)[c], (&r[3].x)[c]);
                        w[2 * c + 1] = pack_e4m3((&r[4].x)[c], (&r[5].x)[c],
                                                 (&r[6].x)[c], (&r[7].x)[c]);
                    }
                    const uint32_t dst = bdst + sec * (B_SEC_W * 4);
                    STS128(dst, w[0], w[1], w[2], w[3]);
                    STS128(dst + 16, w[4], w[5], w[6], w[7]);
                    if (sec < 3) {
#pragma unroll
                        for (int j = 0; j < 8; j++) r[j] = nr[j];
                    }
                }
                MBARRIER_ARRIVE(smem_u32(&bar_full[st]));
            }
        } else {
            // ---------------- A-role: softplus + convert attw --------------
            const int a = pt - 64;   // 0..31
            const int qq = a & 15;   // q-quad 0..15
            const int th = a >> 4;   // 0..1 : owns sections {2th, 2th+1}
            const float4* ap = a4 + (q0 >> 2) + qq;

            float sp_loc[4] = {0.f, 0.f, 0.f, 0.f};

            for (int t = 0; t < NKC / 4; ++t) {
                const int kc = group + 4 * t;
                const int st = kc & (STAGES - 1);
                const int p0 = kc * BK;

                // preload e=0 rows before the wait
                float4 r[8];
                {
                    const int rl = p0 + 8 * th;
#pragma unroll
                    for (int j = 0; j < 4; j++)
                        r[j] = ap[(size_t)(rl + j) * (QQ / 4)];
#pragma unroll
                    for (int j = 0; j < 4; j++)
                        r[4 + j] = ap[(size_t)(rl + 16 + j) * (QQ / 4)];
                }

                MBARRIER_WAIT_PARITY(smem_u32(&bar_empty[st]),
                                     ((kc >> 3) + 1) & 1);
                const uint32_t adst = base + st * STAGE_B + qq * 32;

#pragma unroll
                for (int e = 0; e < 2; e++) {
                    float4 nr[8];
                    if (e == 0) {
                        const int rl = p0 + 8 * th + 4;
#pragma unroll
                        for (int j = 0; j < 4; j++)
                            nr[j] = ap[(size_t)(rl + j) * (QQ / 4)];
#pragma unroll
                        for (int j = 0; j < 4; j++)
                            nr[4 + j] = ap[(size_t)(rl + 16 + j) * (QQ / 4)];
                    }
                    uint32_t w[8];
#pragma unroll
                    for (int c = 0; c < 4; c++) {
                        const float f0 = (&r[0].x)[c], f1 = (&r[1].x)[c];
                        const float f2 = (&r[2].x)[c], f3 = (&r[3].x)[c];
                        const float h0 = (&r[4].x)[c], h1 = (&r[5].x)[c];
                        const float h2 = (&r[6].x)[c], h3 = (&r[7].x)[c];
                        sp_loc[c] += softplus_f(f0) + softplus_f(f1) +
                                     softplus_f(f2) + softplus_f(f3) +
                                     softplus_f(h0) + softplus_f(h1) +
                                     softplus_f(h2) + softplus_f(h3);
                        w[2 * c + 0] = pack_e4m3(f0, f1, f2, f3);
                        w[2 * c + 1] = pack_e4m3(h0, h1, h2, h3);
                    }
                    const uint32_t dst = adst + (2 * th + e) * (A_SEC_W * 4);
                    STS128(dst, w[0], w[1], w[2], w[3]);
                    STS128(dst + 16, w[4], w[5], w[6], w[7]);
                    if (e == 0) {
#pragma unroll
                        for (int j = 0; j < 8; j++) r[j] = nr[j];
                    }
                }
                MBARRIER_ARRIVE(smem_u32(&bar_full[st]));
            }
#pragma unroll
            for (int c = 0; c < 4; c++)
                atomicAdd(&s_sp[qq * 4 + c], sp_loc[c]);
        }
    }

    // ============================ EPILOGUE =============================
    __syncthreads();  // mainloop done; ring SMEM reusable

    // stage logits fp32 (pitch 133) + ids
    {
        float* slog = reinterpret_cast<float*>(dynsmem);
        const float4* lG = reinterpret_cast<const float4*>(
            logits + (size_t)(b * QQ + q0) * CC);
#pragma unroll
        for (int i = 0; i < 4; i++) {
            int idx = tid + i * NTH;
            if (idx < BM * CC / 4) {
                float4 v = lG[idx];
                int m = idx >> 5;
                int fc = (idx & 31) * 4;
                float* dst = slog + m * L_PITCH + fc;
                dst[0] = v.x;
                dst[1] = v.y;
                dst[2] = v.z;
                dst[3] = v.w;
            }
        }
        if (tid < GG) s_ids[tid] = ids[b * GG + tid];
    }
    __syncthreads();

    // SA: sum_c softplus(logits[m,:]) — 8 threads per row (threads 0..511)
    if (tid < 8 * BM) {
        const int row = tid >> 3;
        const int cb = tid & 7;
        const float* lr = reinterpret_cast<const float*>(dynsmem) + row * L_PITCH;
        float ss = 0.f;
#pragma unroll
        for (int k = 0; k < 16; k++) ss += softplus_f(lr[cb + 8 * k]);
        ss += __shfl_xor_sync(0xffffffffu, ss, 1);
        ss += __shfl_xor_sync(0xffffffffu, ss, 2);
        ss += __shfl_xor_sync(0xffffffffu, ss, 4);
        if (cb == 0) s_sa[row] = ss;
    }
    __syncthreads();

    if (warp < 8) {
        // output: cost = s_sp/P + s_sa/C - acc/P - gathered_logit/C
        const float inv_p = 1.0f / PP;
        const float inv_c = 1.0f / CC;
        const float* slog = reinterpret_cast<const float*>(dynsmem);
#pragma unroll
        for (int mt = 0; mt < 2; mt++) {
#pragma unroll
            for (int rr = 0; rr < 2; rr++) {
                const int m = wm * 32 + mt * 16 + g + rr * 8;
                const float Sm = s_sp[m] * inv_p + s_sa[m] * inv_c;
                float* orow = out + (size_t)(b * QQ + q0 + m) * GG;
                const float* lrow = slog + m * L_PITCH;
#pragma unroll
                for (int nt = 0; nt < 8; nt++) {
                    const int n = wn * 64 + nt * 8 + 2 * tig;
                    const float d0 = acc[mt][nt][rr * 2 + 0];
                    const float d1 = acc[mt][nt][rr * 2 + 1];
                    float2 o;
                    o.x = Sm - d0 * inv_p - lrow[s_ids[n]] * inv_c;
                    o.y = Sm - d1 * inv_p - lrow[s_ids[n + 1]] * inv_c;
                    *reinterpret_cast<float2*>(orow + n) = o;
                }
            }
        }
    }
}

// ---------------------------------------------------------------------------
extern "C" void kernel_launch(void* const* d_in, const int* in_sizes, int n_in,
                              void* d_out, int out_size) {
    const float* logits = (const float*)d_in[0];  // [B,Q,C]
    const float* attw = (const float*)d_in[1];    // [B,P,Q]
    const float* onehot = (const float*)d_in[2];  // [B,P,G]
    const int* ids = (const int*)d_in[3];         // [B,G]
    float* out = (float*)d_out;                   // [B,Q,G]

    cudaFuncSetAttribute(cost_kernel,
                         cudaFuncAttributeMaxDynamicSharedMemorySize, SMEM_DYN);

    dim3 grid(QQ / BM, BB);  // 8 x 64 = 512 CTAs
    cost_kernel<<<grid, NTH, SMEM_DYN>>>(logits, attw, onehot, ids, out);
}

// round 17
// speedup vs baseline: 1.2874x; 1.2874x over previous
#include <cuda_runtime.h>
#include <cstdint>

// Problem shapes (fixed by the dataset)
#define BB 64
#define QQ 512
#define CC 128
#define PP 2048
#define GG 256

// Tiling: split G in halves -> 1024 CTAs -> 6.92 waves (98.9% packing)
#define BM 64          // Q tile (M)
#define BN 128         // G tile (half of G)
#define BK 32          // persons per chunk (K of one fp8 MMA)
#define NKC (PP / BK)  // 64 chunks
#define STAGES 8       // SMEM ring depth
#define NTH 512        // 8 consumer warps + 8 producer warps (4 groups x 2)

// Fragment-native fp8 stage layout: A [8 kwords][A_ROWW], B [8 kwords][B_ROWW]
// pitches mod 32 == 8 -> conflict-free LDS.32 / STS (same bank maps as R9)
#define A_ROWW 72                            // words: 64 q + 8 pad
#define B_ROWW 136                           // words: 128 g + 8 pad
#define A_WORDS (8 * A_ROWW)                 // 576
#define STAGE_WORDS (8 * (A_ROWW + B_ROWW))  // 1664 words = 6656 B
#define SMEM_DYN (STAGES * STAGE_WORDS * 4)  // 53248 B

#define L_PITCH 133  // fp32 logits epilogue pitch

// 5-op softplus (validated R10/R12: rel_err 6.43e-5); inputs N(0,1)
__device__ __forceinline__ float softplus_f(float x) {
    float e, l;
    asm("ex2.approx.f32 %0, %1;" : "=f"(e) : "f"(x * 1.4426950408889634f));
    asm("lg2.approx.f32 %0, %1;" : "=f"(l) : "f"(e + 1.0f));
    return 0.6931471805599453f * l;
}

// ---------------------------------------------------------------------------
// PTX helpers
// ---------------------------------------------------------------------------
__device__ __forceinline__ uint32_t smem_u32(const void* p) {
    return (uint32_t)__cvta_generic_to_shared(p);
}

#define MBARRIER_INIT(addr, count)                                 \
    asm volatile("mbarrier.init.shared.b64 [%0], %1;" ::"r"(addr), \
                 "r"((uint32_t)(count))                            \
                 : "memory")

#define MBARRIER_ARRIVE(addr)                                      \
    asm volatile("mbarrier.arrive.shared.b64 _, [%0];" ::"r"(addr) \
                 : "memory")

#define MBARRIER_WAIT_PARITY(mbar_addr, phase_parity)                          \
    do {                                                                       \
        uint32_t _mbar = (uint32_t)(mbar_addr);                                \
        uint32_t _parity = (uint32_t)(phase_parity);                           \
        uint32_t _done;                                                        \
        asm volatile(                                                          \
            "{\n\t"                                                            \
            ".reg .pred p;\n\t"                                                \
            "mbarrier.try_wait.parity.acquire.cta.shared::cta.b64 p, [%1], "   \
            "%2;\n\t"                                                          \
            "selp.b32 %0, 1, 0, p;\n\t"                                        \
            "}"                                                                \
            : "=r"(_done)                                                      \
            : "r"(_mbar), "r"(_parity)                                         \
            : "memory");                                                       \
        if (!_done) {                                                          \
            asm volatile(                                                      \
                "{\n\t"                                                        \
                ".reg .pred P1;\n\t"                                           \
                "WAIT_LOOP_%=:\n\t"                                            \
                "mbarrier.try_wait.parity.acquire.cta.shared::cta.b64 P1, "    \
                "[%0], %1, 0x989680;\n\t"                                      \
                "@P1 bra.uni WAIT_DONE_%=;\n\t"                                \
                "bra.uni WAIT_LOOP_%=;\n\t"                                    \
                "WAIT_DONE_%=:\n\t"                                            \
                "}" ::"r"(_mbar),                                              \
                "r"(_parity)                                                   \
                : "memory");                                                   \
        }                                                                      \
    } while (0)

// pack 4 fp32 -> 4 e4m3 bytes, byte0 = f0 .. byte3 = f3 (validated R9)
__device__ __forceinline__ uint32_t pack_e4m3(float f0, float f1, float f2,
                                              float f3) {
    unsigned short lo, hi;
    asm("cvt.rn.satfinite.e4m3x2.f32 %0, %1, %2;" : "=h"(lo) : "f"(f1), "f"(f0));
    asm("cvt.rn.satfinite.e4m3x2.f32 %0, %1, %2;" : "=h"(hi) : "f"(f3), "f"(f2));
    return (uint32_t)lo | ((uint32_t)hi << 16);
}

#define STS128(addr, w0, w1, w2, w3)                                       \
    asm volatile("st.shared.v4.b32 [%0], {%1, %2, %3, %4};" ::"r"(addr),   \
                 "r"(w0), "r"(w1), "r"(w2), "r"(w3)                        \
                 : "memory")

// fp8 MMA: D(16x8,f32) += A(16x32,e4m3) * B(32x8,e4m3)  (sm_89 baseline op)
__device__ __forceinline__ void mma_e4m3(float* d, const uint32_t* a,
                                         const uint32_t* b) {
    asm volatile(
        "mma.sync.aligned.m16n8k32.row.col.f32.e4m3.e4m3.f32 "
        "{%0,%1,%2,%3}, {%4,%5,%6,%7}, {%8,%9}, {%0,%1,%2,%3};"
        : "+f"(d[0]), "+f"(d[1]), "+f"(d[2]), "+f"(d[3])
        : "r"(a[0]), "r"(a[1]), "r"(a[2]), "r"(a[3]), "r"(b[0]), "r"(b[1]));
}

// ---------------------------------------------------------------------------
// Single fused kernel: fp8 GEMM + softplus(attw) + softplus(logits) + gather
// R9 structure, G split across 2 CTAs (BN=128) for near-perfect wave packing.
// ---------------------------------------------------------------------------
extern "C" __global__ void __launch_bounds__(NTH, 1)
cost_kernel(const float* __restrict__ logits, const float* __restrict__ attw,
            const float* __restrict__ onehot, const int* __restrict__ ids,
            float* __restrict__ out) {
    extern __shared__ __align__(16) char dynsmem[];
    uint32_t* dynw = reinterpret_cast<uint32_t*>(dynsmem);

    __shared__ alignas(8) unsigned long long bar_full[STAGES];
    __shared__ alignas(8) unsigned long long bar_empty[STAGES];
    __shared__ float s_sp[BM];  // sum_p softplus(attw[:,q])
    __shared__ float s_sa[BM];  // sum_c softplus(logits[q,:])
    __shared__ int s_ids[BN];   // this CTA's G-half

    const int tid = threadIdx.x;
    const int lane = tid & 31;
    const int warp = tid >> 5;
    const int qt = blockIdx.x >> 1;
    const int gt = blockIdx.x & 1;
    const int q0 = qt * BM;
    const int g0 = gt * BN;
    const int b = blockIdx.y;

    if (tid < BM) s_sp[tid] = 0.0f;
    if (tid == 0) {
#pragma unroll
        for (int s = 0; s < STAGES; s++) {
            MBARRIER_INIT(smem_u32(&bar_full[s]), 64);  // one producer group
            MBARRIER_INIT(smem_u32(&bar_empty[s]), 8);  // 8 consumer warps
        }
    }
    __syncthreads();

    // accumulators live in consumer warps only (32x32 warp tile)
    float acc[2][4][4];
    const int wm = warp >> 2;  // 0..1 (consumers)
    const int wn = warp & 3;   // 0..3 (32 g each)
    const int g = lane >> 2;   // row-group 0..7
    const int tig = lane & 3;  // thread-in-group

    if (warp < 8) {
        // ===================== CONSUMERS (warps 0..7) ======================
#pragma unroll
        for (int i = 0; i < 2; i++)
#pragma unroll
            for (int j = 0; j < 4; j++)
#pragma unroll
                for (int k = 0; k < 4; k++) acc[i][j][k] = 0.0f;

        for (int kc = 0; kc < NKC; ++kc) {
            const int st = kc & (STAGES - 1);
            MBARRIER_WAIT_PARITY(smem_u32(&bar_full[st]), (kc >> 3) & 1);

            const uint32_t* Aw = dynw + (size_t)st * STAGE_WORDS;
            const uint32_t* Bw = Aw + A_WORDS;

            // A fragments: word[kw=tig][m], pairs (m, m+8); hi-k at kw=tig+4
            uint32_t aF[2][4];
#pragma unroll
            for (int mt = 0; mt < 2; mt++) {
                const uint32_t* plo = Aw + tig * A_ROWW + wm * 32 + mt * 16 + g;
                const uint32_t* phi = plo + 4 * A_ROWW;
                aF[mt][0] = plo[0];
                aF[mt][1] = plo[8];
                aF[mt][2] = phi[0];
                aF[mt][3] = phi[8];
            }
            // B fragments: b0=[kw=tig][n], b1=[kw=tig+4][n]
            uint32_t bF[4][2];
#pragma unroll
            for (int nt = 0; nt < 4; nt++) {
                const uint32_t* pb = Bw + tig * B_ROWW + wn * 32 + nt * 8 + g;
                bF[nt][0] = pb[0];
                bF[nt][1] = pb[4 * B_ROWW];
            }
#pragma unroll
            for (int mt = 0; mt < 2; mt++)
#pragma unroll
                for (int nt = 0; nt < 4; nt++)
                    mma_e4m3(acc[mt][nt], aF[mt], bF[nt]);

            __syncwarp();
            if (lane == 0) MBARRIER_ARRIVE(smem_u32(&bar_empty[st]));
        }
    } else {
        // ===================== PRODUCERS (warps 8..15) =====================
        // 4 groups x 64 threads; group handles kc % 4 == group.
        const int pg = tid - 256;   // 0..255
        const int group = pg >> 6;  // 0..3
        const int pt = pg & 63;     // 0..63 within group
        const int qq = pt & 15;     // A: q-quad 0..15
        const int kp = pt >> 4;     // A: kword-pair 0..3 (kwords 2kp, 2kp+1)
        const int gq = pt & 31;     // B: g-quad 0..31 (within this G-half)
        const int h2 = pt >> 5;     // B: row-half 0..1 (kwords 4*h2..4*h2+3)

        const float4* aG4 =
            reinterpret_cast<const float4*>(attw + (size_t)b * PP * QQ);
        const float4* bG4 =
            reinterpret_cast<const float4*>(onehot + (size_t)b * PP * GG) +
            (g0 >> 2);
        const int q4 = q0 >> 2;

        float sp_loc[4] = {0.f, 0.f, 0.f, 0.f};

        for (int t = 0; t < NKC / 4; ++t) {
            const int kc = group + 4 * t;
            const int st = kc & (STAGES - 1);
            const int p0 = kc * BK;
            uint32_t* Aw = dynw + (size_t)st * STAGE_WORDS;
            uint32_t* Bw = Aw + A_WORDS;

            // ---- A loads: 8 consecutive k-rows at this q-quad ----
            float4 av[8];
#pragma unroll
            for (int i = 0; i < 8; i++)
                av[i] = aG4[(size_t)(p0 + kp * 8 + i) * (QQ / 4) + q4 + qq];

            // ---- A: softplus + k-pack (in-thread, validated R9) ----
            uint32_t aw[8];
#pragma unroll
            for (int h = 0; h < 2; h++) {
#pragma unroll
                for (int c = 0; c < 4; c++) {
                    const float f0 = (&av[4 * h + 0].x)[c];
                    const float f1 = (&av[4 * h + 1].x)[c];
                    const float f2 = (&av[4 * h + 2].x)[c];
                    const float f3 = (&av[4 * h + 3].x)[c];
                    sp_loc[c] += softplus_f(f0) + softplus_f(f1) +
                                 softplus_f(f2) + softplus_f(f3);
                    aw[4 * h + c] = pack_e4m3(f0, f1, f2, f3);
                }
            }

            // ---- B block-0 loads: rows p0+16*h2 .. +7 at g-quad gq ----
            float4 bv[8];
#pragma unroll
            for (int i = 0; i < 8; i++)
                bv[i] = bG4[(size_t)(p0 + 16 * h2 + i) * (GG / 4) + gq];

            // wait until consumers released this stage
            MBARRIER_WAIT_PARITY(smem_u32(&bar_empty[st]), ((kc >> 3) + 1) & 1);

            // ---- A STS: 2x STS.128, words [kw=2kp+h][q = qq*4 .. +3] ----
            {
                uint32_t a0 = smem_u32(Aw + (2 * kp + 0) * A_ROWW + qq * 4);
                STS128(a0, aw[0], aw[1], aw[2], aw[3]);
                uint32_t a1 = smem_u32(Aw + (2 * kp + 1) * A_ROWW + qq * 4);
                STS128(a1, aw[4], aw[5], aw[6], aw[7]);
            }

            // ---- B: 2 blocks of 8 rows (16 rows total), double-buffered ----
#pragma unroll
            for (int blk = 0; blk < 2; blk++) {
                float4 nb[8];
                if (blk == 0) {
#pragma unroll
                    for (int i = 0; i < 8; i++)
                        nb[i] = bG4[(size_t)(p0 + 16 * h2 + 8 + i) * (GG / 4) +
                                    gq];
                }
#pragma unroll
                for (int h = 0; h < 2; h++) {
                    const float4& r0 = bv[4 * h + 0];
                    const float4& r1 = bv[4 * h + 1];
                    const float4& r2 = bv[4 * h + 2];
                    const float4& r3 = bv[4 * h + 3];
                    uint32_t w0 = pack_e4m3(r0.x, r1.x, r2.x, r3.x);
                    uint32_t w1 = pack_e4m3(r0.y, r1.y, r2.y, r3.y);
                    uint32_t w2 = pack_e4m3(r0.z, r1.z, r2.z, r3.z);
                    uint32_t w3 = pack_e4m3(r0.w, r1.w, r2.w, r3.w);
                    const int kw = 4 * h2 + 2 * blk + h;
                    uint32_t dst = smem_u32(Bw + kw * B_ROWW + gq * 4);
                    STS128(dst, w0, w1, w2, w3);
                }
                if (blk == 0) {
#pragma unroll
                    for (int i = 0; i < 8; i++) bv[i] = nb[i];
                }
            }
            // release: arrive orders prior STS before consumers' acquire
            MBARRIER_ARRIVE(smem_u32(&bar_full[st]));
        }

        // softplus(attw) reduction: thread owns q = qq*4 + c (16 contributors)
#pragma unroll
        for (int c = 0; c < 4; c++) atomicAdd(&s_sp[qq * 4 + c], sp_loc[c]);
    }

    // ============================ EPILOGUE =============================
    __syncthreads();  // mainloop done; ring SMEM reusable

    // stage logits fp32 (pitch 133) + ids (this CTA's G-half)
    {
        float* slog = reinterpret_cast<float*>(dynsmem);
        const float4* lG = reinterpret_cast<const float4*>(
            logits + (size_t)(b * QQ + q0) * CC);
#pragma unroll
        for (int i = 0; i < 4; i++) {
            int idx = tid + i * NTH;  // 0..2047 exactly covers 64x128
            float4 v = lG[idx];
            int m = idx >> 5;
            int fc = (idx & 31) * 4;
            float* dst = slog + m * L_PITCH + fc;
            dst[0] = v.x;
            dst[1] = v.y;
            dst[2] = v.z;
            dst[3] = v.w;
        }
        if (tid < BN) s_ids[tid] = ids[b * GG + g0 + tid];
    }
    __syncthreads();

    // SA: sum_c softplus(logits[m,:]) — 8 threads per row
    {
        const int row = tid >> 3;
        const int cb = tid & 7;
        const float* lr = reinterpret_cast<const float*>(dynsmem) + row * L_PITCH;
        float ss = 0.f;
#pragma unroll
        for (int k = 0; k < 16; k++) ss += softplus_f(lr[cb + 8 * k]);
        ss += __shfl_xor_sync(0xffffffffu, ss, 1);
        ss += __shfl_xor_sync(0xffffffffu, ss, 2);
        ss += __shfl_xor_sync(0xffffffffu, ss, 4);
        if (cb == 0) s_sa[row] = ss;
    }
    __syncthreads();

    if (warp < 8) {
        // output: cost = s_sp/P + s_sa/C - acc/P - gathered_logit/C
        const float inv_p = 1.0f / PP;
        const float inv_c = 1.0f / CC;
        const float* slog = reinterpret_cast<const float*>(dynsmem);
#pragma unroll
        for (int mt = 0; mt < 2; mt++) {
#pragma unroll
            for (int rr = 0; rr < 2; rr++) {
                const int m = wm * 32 + mt * 16 + g + rr * 8;
                const float Sm = s_sp[m] * inv_p + s_sa[m] * inv_c;
                float* orow = out + (size_t)(b * QQ + q0 + m) * GG + g0;
                const float* lrow = slog + m * L_PITCH;
#pragma unroll
                for (int nt = 0; nt < 4; nt++) {
                    const int n = wn * 32 + nt * 8 + 2 * tig;  // 0..127 local
                    const float d0 = acc[mt][nt][rr * 2 + 0];
                    const float d1 = acc[mt][nt][rr * 2 + 1];
                    float2 o;
                    o.x = Sm - d0 * inv_p - lrow[s_ids[n]] * inv_c;
                    o.y = Sm - d1 * inv_p - lrow[s_ids[n + 1]] * inv_c;
                    *reinterpret_cast<float2*>(orow + n) = o;
                }
            }
        }
    }
}

// ---------------------------------------------------------------------------
extern "C" void kernel_launch(void* const* d_in, const int* in_sizes, int n_in,
                              void* d_out, int out_size) {
    const float* logits = (const float*)d_in[0];  // [B,Q,C]
    const float* attw = (const float*)d_in[1];    // [B,P,Q]
    const float* onehot = (const float*)d_in[2];  // [B,P,G]
    const int* ids = (const int*)d_in[3];         // [B,G]
    float* out = (float*)d_out;                   // [B,Q,G]

    cudaFuncSetAttribute(cost_kernel,
                         cudaFuncAttributeMaxDynamicSharedMemorySize, SMEM_DYN);

    dim3 grid(16, BB);  // (qt,gt) x batch = 1024 CTAs -> 6.92 waves (98.9%)
    cost_kernel<<<grid, NTH, SMEM_DYN>>>(logits, attw, onehot, ids, out);
}